// round 5
// baseline (speedup 1.0000x reference)
#include <cuda_runtime.h>
#include <math.h>

// Problem constants (fixed by the reference: B=16, N=4096, Z=128)
#define BB 16
#define NN 4096
#define ZZ 128

#define THREADS 512
#define Q 8                     // preds per thread: 512*8 = 4096 = ALL preds of the batch
#define GSPLIT 16               // gt splits per batch
#define GTS (NN / GSPLIT)       // 256 gts per CTA
#define NCTAS (BB * GSPLIT)     // 256
#define NWARPS (THREADS / 32)   // 16

// Encoded row-min keys: zero-init == identity for atomicMax == +inf in min-space.
__device__ unsigned g_rmkey[BB * NN];   // 256KB, stays L2-resident
__device__ float    g_colsum[NCTAS];    // per-CTA complete col-min sums
__device__ int      g_count = 0;

// Monotone-DECREASING float->uint map (min(v) <=> max(key)), identity 0.
//   v >= 0: key = ~bits & 0x7FFFFFFF   (smaller v -> larger key, top bit 0)
//   v <  0: key = bits                 (more negative -> larger key, top bit 1)
__device__ __forceinline__ unsigned enc_min(float v) {
    unsigned b = __float_as_uint(v);
    return (b & 0x80000000u) ? b : (~b & 0x7FFFFFFFu);
}
__device__ __forceinline__ float dec_min(unsigned m) {
    return __uint_as_float((m & 0x80000000u) ? m : (~m & 0x7FFFFFFFu));
}

// FFMA with immediate 1.0 multiplier: rt_SMSP=1 (2x tput vs 3-reg FFMA/FADD)
__device__ __forceinline__ float fma_i1(float a, float c) {
    float d;
    asm("fma.rn.f32 %0, %1, 0f3F800000, %2;" : "=f"(d) : "f"(a), "f"(c));
    return d;
}

// Each CTA: batch b, gt range [split*256, +256), ALL 4096 preds in registers.
// Per eval:  t = ||g||^2 - 2 g.p           (3 FFMA, chain seeded with gw)
//   row-min: mn[q] = min(mn[q], t)          (+ rp[q] folded at emit)
//   col-min: cm    = min(cm, t*1.0 + rp[q]) (imm-FFMA rt=1; cm is full P)
// Row-mins merged across gt-splits via atomicMax on encoded keys; the LAST
// CTA (atomic ticket) folds everything + KL and writes out[0] — no 2nd launch.
__global__ __launch_bounds__(THREADS, 2)
void chamfer_fused(const float* __restrict__ preds,
                   const float* __restrict__ gts,
                   const float* __restrict__ mu,
                   const float* __restrict__ logvar,
                   float* __restrict__ out)
{
    __shared__ float4 sg[GTS];             // 4KB: (-2gx, -2gy, -2gz, ||g||^2)
    __shared__ float  scol[NWARPS * GTS];  // 16KB: per-warp col-mins (race-free)
    __shared__ float  red[THREADS];
    __shared__ int    slast;

    const int split = blockIdx.x;
    const int b     = blockIdx.y;
    const float* __restrict__ pb = preds + b * 3 * NN;
    const float* __restrict__ gb = gts   + b * 3 * NN;

    const int tid = threadIdx.x;
    const int wid = tid >> 5;
    if (tid == 0) slast = 0;

    // Stage this CTA's gts (coalesced per-channel loads, pre-scale by -2)
    for (int i = tid; i < GTS; i += THREADS) {
        const int n = split * GTS + i;
        const float x0 = gb[n];
        const float x1 = gb[NN + n];
        const float x2 = gb[2 * NN + n];
        sg[i] = make_float4(-2.0f * x0, -2.0f * x1, -2.0f * x2,
                            x0 * x0 + x1 * x1 + x2 * x2);
    }

    // This thread's 8 preds in registers
    float px[Q], py[Q], pz[Q], rp[Q], mn[Q];
#pragma unroll
    for (int q = 0; q < Q; q++) {
        const int m = tid + q * THREADS;
        px[q] = pb[m];
        py[q] = pb[NN + m];
        pz[q] = pb[2 * NN + m];
        rp[q] = px[q] * px[q] + py[q] * py[q] + pz[q] * pz[q];
        mn[q] = 3.4e38f;
    }
    __syncthreads();

    // Main sweep, 2 gts per iteration for independent shfl chains
    for (int j = 0; j < GTS; j += 2) {
        const float4 g0 = sg[j];
        const float4 g1 = sg[j + 1];
        float ca0 = 3.4e38f, cb0 = 3.4e38f;
        float ca1 = 3.4e38f, cb1 = 3.4e38f;
#pragma unroll
        for (int q = 0; q < Q; q += 2) {
            float t00 = fmaf(g0.x, px[q],   fmaf(g0.y, py[q],   fmaf(g0.z, pz[q],   g0.w)));
            float t01 = fmaf(g0.x, px[q+1], fmaf(g0.y, py[q+1], fmaf(g0.z, pz[q+1], g0.w)));
            float t10 = fmaf(g1.x, px[q],   fmaf(g1.y, py[q],   fmaf(g1.z, pz[q],   g1.w)));
            float t11 = fmaf(g1.x, px[q+1], fmaf(g1.y, py[q+1], fmaf(g1.z, pz[q+1], g1.w)));
            mn[q]   = fminf(mn[q],   fminf(t00, t10));
            mn[q+1] = fminf(mn[q+1], fminf(t01, t11));
            ca0 = fminf(ca0, fma_i1(t00, rp[q]));
            cb0 = fminf(cb0, fma_i1(t01, rp[q+1]));
            ca1 = fminf(ca1, fma_i1(t10, rp[q]));
            cb1 = fminf(cb1, fma_i1(t11, rp[q+1]));
        }
        float cm0 = fminf(ca0, cb0);
        float cm1 = fminf(ca1, cb1);
#pragma unroll
        for (int off = 16; off > 0; off >>= 1) {
            cm0 = fminf(cm0, __shfl_xor_sync(0xFFFFFFFFu, cm0, off));
            cm1 = fminf(cm1, __shfl_xor_sync(0xFFFFFFFFu, cm1, off));
        }
        scol[wid * GTS + j]     = cm0;  // all lanes same value/address
        scol[wid * GTS + j + 1] = cm1;
    }

    // Merge partial row-mins across gt-splits: encoded atomicMax (exact, no
    // float rounding, order-independent). Spread addresses, coalesced lanes.
#pragma unroll
    for (int q = 0; q < Q; q++) {
        const int p = tid + q * THREADS;
        atomicMax(&g_rmkey[b * NN + p], enc_min(mn[q] + rp[q]));
    }

    __syncthreads();

    // Cross-warp col-min reduce + sum over this CTA's 256 gts
    float s = 0.0f;
    for (int i = tid; i < GTS; i += THREADS) {
        float c = scol[i];
#pragma unroll
        for (int w = 1; w < NWARPS; w++)
            c = fminf(c, scol[w * GTS + i]);
        s += c;
    }
    red[tid] = s;
    __syncthreads();
    for (int off = THREADS / 2; off > 0; off >>= 1) {
        if (tid < off) red[tid] += red[tid + off];
        __syncthreads();
    }

    const int cta = b * GSPLIT + split;
    if (tid == 0) {
        g_colsum[cta] = red[0];
        __threadfence();
        const int old = atomicAdd(&g_count, 1);
        if (old == NCTAS - 1) slast = 1;
    }
    __syncthreads();

    // Ticket-last CTA: fold row-min keys (L2-hot) + col-sums + KL, write
    // the scalar, reset keys/ticket for the next graph replay.
    if (slast) {
        __threadfence();
        float f = 0.0f;
        volatile const unsigned* vk = g_rmkey;
        for (int i = tid; i < BB * NN; i += THREADS) f += dec_min(vk[i]);
        volatile const float* vc = g_colsum;
        for (int i = tid; i < NCTAS; i += THREADS) f += vc[i];
        for (int i = tid; i < BB * ZZ; i += THREADS) {
            const float mm = mu[i];
            const float lv = logvar[i];
            f += -0.5f * (1.0f + lv - mm * mm - expf(lv));
        }
        // Reset keys AFTER consuming them (zero == +inf identity)
        for (int i = tid; i < BB * NN; i += THREADS) g_rmkey[i] = 0u;

        red[tid] = f;
        __syncthreads();
        for (int off = THREADS / 2; off > 0; off >>= 1) {
            if (tid < off) red[tid] += red[tid + off];
            __syncthreads();
        }
        if (tid == 0) {
            out[0] = red[0];
            g_count = 0;   // reset ticket
        }
    }
}

extern "C" void kernel_launch(void* const* d_in, const int* in_sizes, int n_in,
                              void* d_out, int out_size)
{
    const float* preds  = (const float*)d_in[0];   // [16, 3, 4096]
    const float* gts    = (const float*)d_in[1];   // [16, 3, 4096]
    const float* mu     = (const float*)d_in[2];   // [16, 128]
    const float* logvar = (const float*)d_in[3];   // [16, 128]
    float* out = (float*)d_out;

    dim3 grid(GSPLIT, BB);
    chamfer_fused<<<grid, THREADS>>>(preds, gts, mu, logvar, out);
}

// round 6
// speedup vs baseline: 1.1703x; 1.1703x over previous
#include <cuda_runtime.h>
#include <math.h>

// Problem constants (fixed by the reference: B=16, N=4096, Z=128)
#define BB 16
#define NN 4096
#define ZZ 128

#define THREADS 512
#define Q 8                     // preds per thread: 512*8 = 4096 = ALL preds of the batch
#define NCTA_A 296              // 2 CTAs per SM on 148 SMs, perfectly balanced
#define GTSMAX 232              // max gt-chunk (<=228 actual, padded)
#define NWARPS (THREADS / 32)   // 16
#define NCTA_B 64

// Encoded row-min keys: zero-init == identity for atomicMax == +inf in min-space.
__device__ unsigned g_rmkey[BB * NN];   // 256KB, L2-resident
__device__ float    g_colsum[NCTA_A];   // per-CTA complete col-min sums
__device__ float    g_partB[NCTA_B];    // finish-kernel partials
__device__ int      g_count = 0;

// Monotone-DECREASING float->uint map (min(v) <=> max(key)), identity 0.
__device__ __forceinline__ unsigned enc_min(float v) {
    unsigned b = __float_as_uint(v);
    return (b & 0x80000000u) ? b : (~b & 0x7FFFFFFFu);
}
__device__ __forceinline__ float dec_min(unsigned m) {
    return __uint_as_float((m & 0x80000000u) ? m : (~m & 0x7FFFFFFFu));
}

// FFMA with immediate 1.0 multiplier: rt_SMSP=1
__device__ __forceinline__ float fma_i1(float a, float c) {
    float d;
    asm("fma.rn.f32 %0, %1, 0f3F800000, %2;" : "=f"(d) : "f"(a), "f"(c));
    return d;
}

// Kernel A: CTA = (batch, balanced gt-chunk), ALL 4096 preds in registers.
// Per eval:  t = ||g||^2 - 2 g.p           (3 FFMA, chain seeded with gw)
//   row-min: mn[q] = min(mn[q], t)          (+ rp[q] folded at emit, atomicMax-merged)
//   col-min: cm    = min(cm, t*1.0 + rp[q]) (imm-FFMA; complete within CTA)
// 296 CTAs = exactly 2 waves-free full occupancy; chunk sizes differ by <1%.
__global__ __launch_bounds__(THREADS, 2)
void chamfer_main(const float* __restrict__ preds,
                  const float* __restrict__ gts)
{
    __shared__ float4 sg[GTSMAX];             // (-2gx, -2gy, -2gz, ||g||^2)
    __shared__ float  scol[NWARPS * GTSMAX];  // per-warp col-mins (race-free)
    __shared__ float  red[THREADS];

    // Balanced (batch, chunk) assignment: batches 0-7 -> 19 CTAs, 8-15 -> 18.
    const int cta = blockIdx.x;
    int batch, idx, C;
    if (cta < 152) { batch = cta / 19;        idx = cta % 19;         C = 19; }
    else           { batch = 8 + (cta - 152) / 18; idx = (cta - 152) % 18; C = 18; }
    const int gA  = 2 * ((idx * (NN / 2)) / C);        // even start
    const int gB  = 2 * (((idx + 1) * (NN / 2)) / C);  // even end
    const int cnt = gB - gA;                            // even, <= 228

    const float* __restrict__ pb = preds + batch * 3 * NN;
    const float* __restrict__ gb = gts   + batch * 3 * NN;

    const int tid = threadIdx.x;
    const int wid = tid >> 5;

    // Stage this CTA's gt chunk (coalesced per-channel loads, pre-scale by -2)
    for (int i = tid; i < cnt; i += THREADS) {
        const int n = gA + i;
        const float x0 = gb[n];
        const float x1 = gb[NN + n];
        const float x2 = gb[2 * NN + n];
        sg[i] = make_float4(-2.0f * x0, -2.0f * x1, -2.0f * x2,
                            x0 * x0 + x1 * x1 + x2 * x2);
    }

    // This thread's 8 preds in registers
    float px[Q], py[Q], pz[Q], rp[Q], mn[Q];
#pragma unroll
    for (int q = 0; q < Q; q++) {
        const int m = tid + q * THREADS;
        px[q] = pb[m];
        py[q] = pb[NN + m];
        pz[q] = pb[2 * NN + m];
        rp[q] = px[q] * px[q] + py[q] * py[q] + pz[q] * pz[q];
        mn[q] = 3.4e38f;
    }
    __syncthreads();

    // Main sweep, 2 gts per iteration for independent shfl chains
    for (int j = 0; j < cnt; j += 2) {
        const float4 g0 = sg[j];
        const float4 g1 = sg[j + 1];
        float ca0 = 3.4e38f, cb0 = 3.4e38f;
        float ca1 = 3.4e38f, cb1 = 3.4e38f;
#pragma unroll
        for (int q = 0; q < Q; q += 2) {
            float t00 = fmaf(g0.x, px[q],   fmaf(g0.y, py[q],   fmaf(g0.z, pz[q],   g0.w)));
            float t01 = fmaf(g0.x, px[q+1], fmaf(g0.y, py[q+1], fmaf(g0.z, pz[q+1], g0.w)));
            float t10 = fmaf(g1.x, px[q],   fmaf(g1.y, py[q],   fmaf(g1.z, pz[q],   g1.w)));
            float t11 = fmaf(g1.x, px[q+1], fmaf(g1.y, py[q+1], fmaf(g1.z, pz[q+1], g1.w)));
            mn[q]   = fminf(mn[q],   fminf(t00, t10));
            mn[q+1] = fminf(mn[q+1], fminf(t01, t11));
            ca0 = fminf(ca0, fma_i1(t00, rp[q]));
            cb0 = fminf(cb0, fma_i1(t01, rp[q+1]));
            ca1 = fminf(ca1, fma_i1(t10, rp[q]));
            cb1 = fminf(cb1, fma_i1(t11, rp[q+1]));
        }
        float cm0 = fminf(ca0, cb0);
        float cm1 = fminf(ca1, cb1);
#pragma unroll
        for (int off = 16; off > 0; off >>= 1) {
            cm0 = fminf(cm0, __shfl_xor_sync(0xFFFFFFFFu, cm0, off));
            cm1 = fminf(cm1, __shfl_xor_sync(0xFFFFFFFFu, cm1, off));
        }
        scol[wid * GTSMAX + j]     = cm0;  // all lanes same value/address
        scol[wid * GTSMAX + j + 1] = cm1;
    }

    // Merge partial row-mins across gt-chunks: encoded atomicMax (exact,
    // order-independent). Spread addresses, coalesced lanes.
#pragma unroll
    for (int q = 0; q < Q; q++) {
        const int p = tid + q * THREADS;
        atomicMax(&g_rmkey[batch * NN + p], enc_min(mn[q] + rp[q]));
    }

    __syncthreads();

    // Cross-warp col-min reduce + sum over this CTA's gts
    float s = 0.0f;
    for (int i = tid; i < cnt; i += THREADS) {
        float c = scol[i];
#pragma unroll
        for (int w = 1; w < NWARPS; w++)
            c = fminf(c, scol[w * GTSMAX + i]);
        s += c;
    }
    red[tid] = s;
    __syncthreads();
    for (int off = THREADS / 2; off > 0; off >>= 1) {
        if (tid < off) red[tid] += red[tid + off];
        __syncthreads();
    }
    if (tid == 0) g_colsum[cta] = red[0];
}

// Kernel B: fold 65K L2-hot row-min keys (each CTA resets its own range),
// ticket-last CTA adds col-sums + KL, writes the scalar.
__global__ __launch_bounds__(256)
void chamfer_finish(const float* __restrict__ mu,
                    const float* __restrict__ logvar,
                    float* __restrict__ out)
{
    __shared__ float red[256];
    __shared__ int   slast;

    const int tid  = threadIdx.x;
    const int base = blockIdx.x * 1024;     // 64 CTAs x 1024 keys
    if (tid == 0) slast = 0;

    float s = 0.0f;
#pragma unroll
    for (int k = 0; k < 4; k++) {
        const int i = base + tid + k * 256;
        s += dec_min(g_rmkey[i]);
        g_rmkey[i] = 0u;                    // reset own keys (zero == +inf)
    }

    red[tid] = s;
    __syncthreads();
    for (int off = 128; off > 0; off >>= 1) {
        if (tid < off) red[tid] += red[tid + off];
        __syncthreads();
    }
    if (tid == 0) {
        g_partB[blockIdx.x] = red[0];
        __threadfence();
        const int old = atomicAdd(&g_count, 1);
        if (old == NCTA_B - 1) slast = 1;
    }
    __syncthreads();

    if (slast) {
        __threadfence();
        float f = 0.0f;
        volatile const float* vp = g_partB;
        for (int i = tid; i < NCTA_B; i += 256) f += vp[i];
        volatile const float* vc = g_colsum;
        for (int i = tid; i < NCTA_A; i += 256) f += vc[i];
        for (int i = tid; i < BB * ZZ; i += 256) {
            const float mm = mu[i];
            const float lv = logvar[i];
            f += -0.5f * (1.0f + lv - mm * mm - expf(lv));
        }
        red[tid] = f;
        __syncthreads();
        for (int off = 128; off > 0; off >>= 1) {
            if (tid < off) red[tid] += red[tid + off];
            __syncthreads();
        }
        if (tid == 0) {
            out[0] = red[0];
            g_count = 0;   // reset ticket for next graph replay
        }
    }
}

extern "C" void kernel_launch(void* const* d_in, const int* in_sizes, int n_in,
                              void* d_out, int out_size)
{
    const float* preds  = (const float*)d_in[0];   // [16, 3, 4096]
    const float* gts    = (const float*)d_in[1];   // [16, 3, 4096]
    const float* mu     = (const float*)d_in[2];   // [16, 128]
    const float* logvar = (const float*)d_in[3];   // [16, 128]
    float* out = (float*)d_out;

    chamfer_main<<<NCTA_A, THREADS>>>(preds, gts);
    chamfer_finish<<<NCTA_B, 256>>>(mu, logvar, out);
}